// round 15
// baseline (speedup 1.0000x reference)
#include <cuda_runtime.h>
#include <cuda_fp16.h>
#include <cstdint>
#include <cstddef>

// ---------------- problem constants ----------------
#define EMBED   4096
#define RPT     1024
#define NTILES  4
#define OUTF    4096
#define MTOK    8192            // B*S tokens

// ---------------- GEMM tiling ----------------
#define BK 64                   // 64 fp16 = 128B rows -> SW128 swizzle
#define NCHUNK (EMBED / BK)     // 64
#define NTG 128                 // threads (4 warps)
#define NSTAGE 3
#define BMc 128
#define BNc 128
#define STAGE_BYTES ((uint32_t)(BMc + BNc) * 128)   // 32KB
#define SMEM_DYN (NSTAGE * STAGE_BYTES + 1024)      // ~97KB -> 2 CTAs/SM

// warp layout: 4 warps = 2 (M) x 2 (N); warp tile 64x64
#define NMF 4
#define NNF 8
#define WMH 64
#define WNH 64

// block-id ranges (single launch, in-order dispatch)
#define NB_GATH 64              // gather fat blocks   [0, 64)
#define NB_TRAN 256             // transpose fat blocks [64, 320), t-major
#define NB_CONV 64              // conv-x fat blocks    [320, 384)
#define NB_PREP (NB_GATH + NB_TRAN + NB_CONV)
#define N_DEC   1024            // decode tiles         [384, 1408)
#define N_LIN   2048            // linear tiles         [1408, 3456)
#define N_BLKS  (NB_PREP + N_DEC + N_LIN)

// readiness counters: [0,32) w_ready, [32,64) aready, [64,68) rready, 68 xready
#define CTR_W 0
#define CTR_A 32
#define CTR_R 64
#define CTR_X 68
#define NCTR  69
__device__ int g_ctr[NCTR];

// ---------------- device scratch (fp16) ----------------
__device__ __half g_Xh[(size_t)MTOK * EMBED];             // x rounded fp16 (64MB)
__device__ __half g_Ah[(size_t)OUTF * EMBED];             // gathered cw fp16 (32MB)
__device__ __half g_Rh[(size_t)NTILES * EMBED * EMBED];   // R^T single fp16 (128MB)
__device__ __half g_Wh[(size_t)OUTF * EMBED];             // decoded W*256 fp16 (32MB)

// ---------------- helpers ----------------
__device__ __forceinline__ uint32_t smem_u32(const void* p) {
    uint32_t a;
    asm("{ .reg .u64 t; cvta.to.shared.u64 t, %1; cvt.u32.u64 %0, t; }" : "=r"(a) : "l"(p));
    return a;
}
__device__ __forceinline__ uint32_t swz(uint32_t b) { return b ^ ((b >> 3) & 0x70); }

__device__ __forceinline__ void ldsm4(uint32_t& r0, uint32_t& r1, uint32_t& r2, uint32_t& r3,
                                      uint32_t addr) {
    asm volatile("ldmatrix.sync.aligned.m8n8.x4.shared.b16 {%0,%1,%2,%3}, [%4];"
                 : "=r"(r0), "=r"(r1), "=r"(r2), "=r"(r3) : "r"(addr));
}
__device__ __forceinline__ void mma16816(float* c, const uint32_t* a, const uint32_t* b) {
    asm volatile(
        "mma.sync.aligned.m16n8k16.row.col.f32.f16.f16.f32 "
        "{%0,%1,%2,%3}, {%4,%5,%6,%7}, {%8,%9}, {%0,%1,%2,%3};"
        : "+f"(c[0]), "+f"(c[1]), "+f"(c[2]), "+f"(c[3])
        : "r"(a[0]), "r"(a[1]), "r"(a[2]), "r"(a[3]), "r"(b[0]), "r"(b[1]));
}
__device__ __forceinline__ void cpasync16(uint32_t dst, const void* src) {
    uint64_t g;
    asm("cvta.to.global.u64 %0, %1;" : "=l"(g) : "l"(src));
    asm volatile("cp.async.cg.shared.global [%0], [%1], 16;" :: "r"(dst), "l"(g));
}
#define CP_COMMIT() asm volatile("cp.async.commit_group;" ::: "memory")
#define CP_WAIT1()  asm volatile("cp.async.wait_group 1;" ::: "memory")

__device__ __forceinline__ uint32_t pack2(__half a, __half b) {
    return (uint32_t)__half_as_ushort(a) | ((uint32_t)__half_as_ushort(b) << 16);
}
__device__ __forceinline__ bool indices_are_i64(const int* __restrict__ p) {
    bool is64 = true;
#pragma unroll
    for (int i = 0; i < 8; ++i) is64 = is64 && (p[2 * i + 1] == 0);
    return is64;
}
__device__ __forceinline__ void spin_until(int idx, int target) {
    while (atomicAdd(&g_ctr[idx], 0) < target) __nanosleep(128);
}

// ---------------------------------------------------------------------------
// Mega-kernel: fat prep + dependency-gated GEMM tiles, one launch.
// ---------------------------------------------------------------------------
__global__ __launch_bounds__(NTG, 2)
void mega_kernel(const float* __restrict__ x,
                 const float* __restrict__ codewords,
                 const int*   __restrict__ idx_raw,
                 const float* __restrict__ rot,
                 const float* __restrict__ bias,
                 float*       __restrict__ out,
                 const float* __restrict__ scales)
{
    extern __shared__ char smraw[];
    const int id  = blockIdx.x;
    const int tid = threadIdx.x;

    // ==================== gather fat blocks [0, 64) ====================
    if (id < NB_GATH) {
        const int r0 = id * 64;
        const bool is64 = indices_are_i64(idx_raw);
#pragma unroll 1
        for (int rr = 0; rr < 64; ++rr) {
            const int r = r0 + rr;
            const int cidx = is64 ? idx_raw[2 * r] : idx_raw[r];
            const float* __restrict__ src = codewords + (size_t)cidx * EMBED;
#pragma unroll
            for (int j = 0; j < 8; ++j) {
                const int e4 = tid + j * NTG;             // 0..1023
                float4 v = *reinterpret_cast<const float4*>(src + e4 * 4);
                uint2 h;
                h.x = pack2(__float2half_rn(v.x), __float2half_rn(v.y));
                h.y = pack2(__float2half_rn(v.z), __float2half_rn(v.w));
                *reinterpret_cast<uint2*>(g_Ah + (size_t)r * EMBED + e4 * 4) = h;
            }
        }
        __threadfence();
        __syncthreads();
        if (tid == 0) atomicAdd(&g_ctr[CTR_A + (id >> 1)], 1);   // target 2 per rb
        return;
    }

    // ==================== transpose fat blocks [64, 320), t-major ====================
    if (id < NB_GATH + NB_TRAN) {
        const int fb  = id - NB_GATH;        // 0..255
        const int t   = fb >> 6;             // 0..3
        const int sub = fb & 63;             // 0..63
        float (*sm)[133] = reinterpret_cast<float (*)[133]>(smraw);
#pragma unroll 1
        for (int i = 0; i < 64; ++i) {
            const int n  = sub * 64 + i;     // thin tile within t: 0..4095
            const int xb = n & 31;           // e block (128 wide)
            const int yb = n >> 5;           // d block (32 wide): 0..127
            // load 32 d-rows x 128 e (coalesced float4)
#pragma unroll
            for (int p = 0; p < 8; ++p) {
                const int dd = p * 4 + (tid >> 5);
                const int e4 = tid & 31;
                float4 v = *reinterpret_cast<const float4*>(
                    rot + ((size_t)t * EMBED + yb * 32 + dd) * EMBED + xb * 128 + e4 * 4);
                sm[dd][e4 * 4 + 0] = v.x;
                sm[dd][e4 * 4 + 1] = v.y;
                sm[dd][e4 * 4 + 2] = v.z;
                sm[dd][e4 * 4 + 3] = v.w;
            }
            __syncthreads();
            const int dg = tid & 3;
#pragma unroll
            for (int p = 0; p < 4; ++p) {
                const int e = (tid >> 2) + p * 32;
                uint4 w;
                uint32_t* wp = reinterpret_cast<uint32_t*>(&w);
#pragma unroll
                for (int j = 0; j < 4; ++j) {
                    float f0 = sm[dg * 8 + 2 * j][e];
                    float f1 = sm[dg * 8 + 2 * j + 1][e];
                    wp[j] = pack2(__float2half_rn(f0), __float2half_rn(f1));
                }
                size_t o = (size_t)t * EMBED * EMBED + (size_t)(xb * 128 + e) * EMBED
                         + yb * 32 + dg * 8;
                *reinterpret_cast<uint4*>(g_Rh + o) = w;
            }
            __syncthreads();
        }
        __threadfence();
        __syncthreads();
        if (tid == 0) atomicAdd(&g_ctr[CTR_R + t], 1);           // target 64 per t
        return;
    }

    // ==================== conv-x fat blocks [320, 384) ====================
    if (id < NB_PREP) {
        const int c = id - NB_GATH - NB_TRAN;                    // 0..63
        const size_t base = (size_t)c * 131072;                  // float4 units
#pragma unroll 8
        for (int j = 0; j < 1024; ++j) {
            const size_t f4 = base + tid + (size_t)j * NTG;
            float4 v = *reinterpret_cast<const float4*>(x + f4 * 4);
            uint2 h;
            h.x = pack2(__float2half_rn(v.x), __float2half_rn(v.y));
            h.y = pack2(__float2half_rn(v.z), __float2half_rn(v.w));
            *reinterpret_cast<uint2*>(g_Xh + f4 * 4) = h;
        }
        __threadfence();
        __syncthreads();
        if (tid == 0) atomicAdd(&g_ctr[CTR_X], 1);               // target 64
        return;
    }

    // ==================== GEMM tiles ====================
    constexpr uint32_t OFF_A0 = 0;
    constexpr uint32_t OFF_B0 = (uint32_t)BMc * 128;

    const uint32_t sraw = smem_u32(smraw);
    const uint32_t sb   = (sraw + 1023u) & ~1023u;

    const int wid  = tid >> 5;
    const int lane = tid & 31;
    const int wm   = wid & 1;
    const int wn   = wid >> 1;
    const int k16   = tid & 7;
    const int rbase = tid >> 3;

    const int gid = id - NB_PREP;
    const bool dec = (gid < N_DEC);
    int bm, bn, blk;
    const __half* __restrict__ A;
    const __half* __restrict__ B;
    if (dec) {
        blk = gid >> 5;                        // W row-block
        bn  = (gid & 31) << 7;
        bm  = blk << 7;
        A = g_Ah;
        B = g_Rh + ((size_t)(bm >> 10) << 24); // t * 4096 * 4096
        if (tid == 0) {
            spin_until(CTR_A + blk, 2);        // gathered rows ready
            spin_until(CTR_R + (blk >> 3), 64);// R^T tile ready
            __threadfence();
        }
        __syncthreads();
    } else {
        const int lid = gid - N_DEC;
        blk = lid >> 6;                        // n-block (slow axis: ready earliest)
        bm  = (lid & 63) << 7;
        bn  = blk << 7;
        A = g_Xh;
        B = g_Wh;
        if (tid == 0) {
            spin_until(CTR_X, 64);             // x converted
            spin_until(CTR_W + blk, 32);       // W row-block decoded
            __threadfence();
        }
        __syncthreads();
    }

    float acc[NMF][NNF][4];
#pragma unroll
    for (int i = 0; i < NMF; ++i)
#pragma unroll
        for (int j = 0; j < NNF; ++j)
#pragma unroll
            for (int q = 0; q < 4; ++q) acc[i][j][q] = 0.0f;

    auto issue = [&](int c, int stage) {
        const uint32_t st = sb + (uint32_t)stage * STAGE_BYTES;
        const size_t kofs = (size_t)c * BK + k16 * 8;
#pragma unroll
        for (int i = 0; i < BMc / 16; ++i) {
            const int row = rbase + i * 16;
            const uint32_t d = swz((uint32_t)(row * 128 + k16 * 16));
            cpasync16(st + OFF_A0 + d, A + (size_t)(bm + row) * EMBED + kofs);
        }
#pragma unroll
        for (int i = 0; i < BNc / 16; ++i) {
            const int row = rbase + i * 16;
            const uint32_t d = swz((uint32_t)(row * 128 + k16 * 16));
            cpasync16(st + OFF_B0 + d, B + (size_t)(bn + row) * EMBED + kofs);
        }
    };

    issue(0, 0); CP_COMMIT();
    issue(1, 1); CP_COMMIT();

    int stage = 0;
#pragma unroll 1
    for (int c = 0; c < NCHUNK; ++c) {
        CP_WAIT1();
        __syncthreads();
        if (c + 2 < NCHUNK) issue(c + 2, (stage + 2) % NSTAGE);
        CP_COMMIT();

        const uint32_t st = sb + (uint32_t)stage * STAGE_BYTES;
#pragma unroll
        for (int ks = 0; ks < 4; ++ks) {
            uint32_t b0[NNF * 2];
#pragma unroll
            for (int np = 0; np < NNF / 2; ++np) {
                const int rB = wn * WNH + np * 16 + (lane & 7) + ((lane >> 4) & 1) * 8;
                const uint32_t off = swz((uint32_t)(rB * 128 + ks * 32 + ((lane >> 3) & 1) * 16));
                ldsm4(b0[np * 4 + 0], b0[np * 4 + 1], b0[np * 4 + 2], b0[np * 4 + 3],
                      st + OFF_B0 + off);
            }
#pragma unroll
            for (int mf = 0; mf < NMF; ++mf) {
                const int rA = wm * WMH + mf * 16 + (lane & 15);
                const uint32_t off = swz((uint32_t)(rA * 128 + ks * 32 + (lane >> 4) * 16));
                uint32_t a0[4];
                ldsm4(a0[0], a0[1], a0[2], a0[3], st + OFF_A0 + off);
#pragma unroll
                for (int nf = 0; nf < NNF; ++nf)
                    mma16816(acc[mf][nf], a0, &b0[(nf >> 1) * 4 + (nf & 1) * 2]);
            }
        }
        stage = (stage + 1) % NSTAGE;
    }

    // ---- epilogue ----
    if (dec) {
        const float s = scales[bm >> 10] * 256.0f;
#pragma unroll
        for (int nf = 0; nf < NNF; ++nf) {
            const int col = bn + wn * WNH + nf * 8 + (lane & 3) * 2;
#pragma unroll
            for (int mf = 0; mf < NMF; ++mf) {
                const int row = bm + wm * WMH + mf * 16 + (lane >> 2);
                uint32_t p0 = pack2(__float2half_rn(acc[mf][nf][0] * s),
                                    __float2half_rn(acc[mf][nf][1] * s));
                uint32_t p1 = pack2(__float2half_rn(acc[mf][nf][2] * s),
                                    __float2half_rn(acc[mf][nf][3] * s));
                *reinterpret_cast<uint32_t*>(g_Wh + (size_t)row * EMBED + col)       = p0;
                *reinterpret_cast<uint32_t*>(g_Wh + (size_t)(row + 8) * EMBED + col) = p1;
            }
        }
        __threadfence();
        __syncthreads();
        if (tid == 0) atomicAdd(&g_ctr[CTR_W + blk], 1);
    } else {
        constexpr float INV = 1.0f / 256.0f;
#pragma unroll
        for (int nf = 0; nf < NNF; ++nf) {
            const int col = bn + wn * WNH + nf * 8 + (lane & 3) * 2;
            const float b0 = bias[col], b1 = bias[col + 1];
#pragma unroll
            for (int mf = 0; mf < NMF; ++mf) {
                const int row = bm + wm * WMH + mf * 16 + (lane >> 2);
                float2 v0 = make_float2(acc[mf][nf][0] * INV + b0, acc[mf][nf][1] * INV + b1);
                float2 v1 = make_float2(acc[mf][nf][2] * INV + b0, acc[mf][nf][3] * INV + b1);
                *reinterpret_cast<float2*>(out + (size_t)row * OUTF + col)       = v0;
                *reinterpret_cast<float2*>(out + (size_t)(row + 8) * OUTF + col) = v1;
            }
        }
    }
}

// ---------------------------------------------------------------------------
// Launch. Inputs: x, codewords, indices, rotations, scales, bias.
// ---------------------------------------------------------------------------
extern "C" void kernel_launch(void* const* d_in, const int* in_sizes, int n_in,
                              void* d_out, int out_size)
{
    const float* x         = (const float*)d_in[0];
    const float* codewords = (const float*)d_in[1];
    const int*   indices   = (const int*)  d_in[2];
    const float* rotations = (const float*)d_in[3];
    const float* scales    = (const float*)d_in[4];
    const float* bias      = (const float*)d_in[5];
    float*       out       = (float*)d_out;

    cudaFuncSetAttribute(mega_kernel, cudaFuncAttributeMaxDynamicSharedMemorySize, SMEM_DYN);

    void* pc = nullptr;
    cudaGetSymbolAddress(&pc, g_ctr);
    cudaMemsetAsync(pc, 0, NCTR * sizeof(int));    // graph-capturable memset node

    mega_kernel<<<N_BLKS, NTG, SMEM_DYN>>>(x, codewords, indices, rotations,
                                           bias, out, scales);
}